// round 5
// baseline (speedup 1.0000x reference)
#include <cuda_runtime.h>
#include <cuda_bf16.h>
#include <cstdint>
#include <math.h>

#define HID  2048
#define SEQ  2048
#define BATCH 4
#define NQKV 6144   // 3*HID

// GEMM tile config: 128x256 CTA tile, BK=32, 8 warps of 64x64
#define BM 128
#define BN 256
#define BK 32
#define STAGES 5
#define ASTRIDE 5120                        // 128 rows * 40 elems
#define BSTRIDE 10240                       // max(256*40, 32*264) elems
#define STAGE_ELEMS (ASTRIDE + BSTRIDE)     // 15360
#define SMEM_BYTES (STAGES * STAGE_ELEMS * 2)  // 153600

// ---------------- scratch (device globals; no allocations allowed) ----------
__device__ __align__(16) __nv_bfloat16 g_xn  [BATCH * SEQ * HID];    // 32 MB
__device__ __align__(16) __nv_bfloat16 g_wqkv[HID * NQKV];           // 24 MB
__device__ __align__(16) __nv_bfloat16 g_wo  [HID * HID];            //  8 MB
__device__ __align__(16) __nv_bfloat16 g_qkv [BATCH * SEQ * NQKV];   // 96 MB
__device__ __align__(16) float         g_sc  [BATCH * SEQ * SEQ];    // 64 MB
__device__ __align__(16) __nv_bfloat16 g_pr  [BATCH * SEQ * SEQ];    // 32 MB
__device__ __align__(16) __nv_bfloat16 g_av  [BATCH * SEQ * HID];    // 32 MB

// ---------------- helpers ----------------------------------------------------
__device__ __forceinline__ void cpa16(uint32_t dst, const void* src) {
    asm volatile("cp.async.cg.shared.global [%0], [%1], 16;" :: "r"(dst), "l"(src));
}
__device__ __forceinline__ void cpa_commit() {
    asm volatile("cp.async.commit_group;");
}
template <int N>
__device__ __forceinline__ void cpa_wait() {
    asm volatile("cp.async.wait_group %0;" :: "n"(N));
}

// ---------------- fp32 -> bf16 convert ---------------------------------------
__global__ void cvt_kernel(const float4* __restrict__ in, uint32_t* __restrict__ out, int n4) {
    int i = blockIdx.x * blockDim.x + threadIdx.x;
    if (i < n4) {
        float4 v = in[i];
        __nv_bfloat162 a = __float22bfloat162_rn(make_float2(v.x, v.y));
        __nv_bfloat162 b = __float22bfloat162_rn(make_float2(v.z, v.w));
        out[i * 2 + 0] = *reinterpret_cast<uint32_t*>(&a);
        out[i * 2 + 1] = *reinterpret_cast<uint32_t*>(&b);
    }
}

// ---------------- LayerNorm: one block per row, bf16 out ---------------------
__global__ void ln_kernel(const float* __restrict__ x,
                          const float* __restrict__ gamma,
                          const float* __restrict__ beta,
                          __nv_bfloat16* __restrict__ out) {
    const int row = blockIdx.x;
    const float* xr = x + (size_t)row * HID;
    __nv_bfloat16* orow = out + (size_t)row * HID;
    const int tid = threadIdx.x;

    float v[8];
    float s = 0.f, s2 = 0.f;
#pragma unroll
    for (int i = 0; i < 8; i++) {
        float val = xr[tid + i * 256];
        v[i] = val; s += val; s2 += val * val;
    }
    __shared__ float red[2][8];
#pragma unroll
    for (int o = 16; o > 0; o >>= 1) {
        s  += __shfl_down_sync(0xffffffffu, s,  o);
        s2 += __shfl_down_sync(0xffffffffu, s2, o);
    }
    const int w = tid >> 5, l = tid & 31;
    if (l == 0) { red[0][w] = s; red[1][w] = s2; }
    __syncthreads();
    if (w == 0) {
        float a  = red[0][l & 7];
        float b2 = red[1][l & 7];
#pragma unroll
        for (int o = 4; o > 0; o >>= 1) {
            a  += __shfl_down_sync(0xffffffffu, a,  o);
            b2 += __shfl_down_sync(0xffffffffu, b2, o);
        }
        if (l == 0) { red[0][0] = a; red[1][0] = b2; }
    }
    __syncthreads();
    const float mean = red[0][0] * (1.f / HID);
    const float var  = red[1][0] * (1.f / HID) - mean * mean;
    const float rstd = rsqrtf(var + 1e-5f);
#pragma unroll
    for (int i = 0; i < 8; i++) {
        int h = tid + i * 256;
        orow[h] = __float2bfloat16((v[i] - mean) * rstd * gamma[h] + beta[h]);
    }
}

// ---------------- causal softmax: fp32 scores in, bf16 probs out -------------
__global__ void softmax_kernel(float* __restrict__ sc,
                               __nv_bfloat16* __restrict__ pr, float scale) {
    const int row = blockIdx.x;            // b*SEQ + q
    const int q = row & (SEQ - 1);
    float* p = sc + (size_t)row * SEQ;
    __nv_bfloat16* po = pr + (size_t)row * SEQ;
    const int n = q + 1;
    const int tid = threadIdx.x;
    __shared__ float red[8];

    float mx = -1e30f;
    for (int t = tid; t < n; t += 256) mx = fmaxf(mx, p[t] * scale);
#pragma unroll
    for (int o = 16; o > 0; o >>= 1) mx = fmaxf(mx, __shfl_down_sync(0xffffffffu, mx, o));
    if ((tid & 31) == 0) red[tid >> 5] = mx;
    __syncthreads();
    if (tid < 32) {
        float a = red[tid & 7];
#pragma unroll
        for (int o = 4; o > 0; o >>= 1) a = fmaxf(a, __shfl_down_sync(0xffffffffu, a, o));
        if (tid == 0) red[0] = a;
    }
    __syncthreads();
    mx = red[0];
    __syncthreads();

    float sum = 0.f;
    for (int t = tid; t < n; t += 256) {
        float e = __expf(p[t] * scale - mx);
        p[t] = e;
        sum += e;
    }
#pragma unroll
    for (int o = 16; o > 0; o >>= 1) sum += __shfl_down_sync(0xffffffffu, sum, o);
    if ((tid & 31) == 0) red[tid >> 5] = sum;
    __syncthreads();
    if (tid < 32) {
        float a = red[tid & 7];
#pragma unroll
        for (int o = 4; o > 0; o >>= 1) a += __shfl_down_sync(0xffffffffu, a, o);
        if (tid == 0) red[0] = a;
    }
    __syncthreads();
    const float inv = 1.f / red[0];
    for (int t = tid; t < n; t += 256) po[t] = __float2bfloat16(p[t] * inv);
    for (int t = n + tid; t < SEQ; t += 256) po[t] = __float2bfloat16(0.f);
}

// ---------------- bf16 tensor-core GEMM (5-stage, 128x256 tile) --------------
// C[M,N] = A[M,K] @ B. A row-major bf16 (lda).
// BKMAJ=true:  B stored [N,K] k-contig (ldb) -> A @ B^T.
// BKMAJ=false: B stored [K,N] n-contig (ldb).
// EPI: 0 = fp32 out, 1 = fp32 out + residual R, 2 = bf16 out.
// 8 warps, warp tile 64x64, m16n8k16 bf16 mma, 1 CTA/SM.
template <bool BKMAJ, int EPI, bool CSKIP, bool CKLIM>
__global__ void __launch_bounds__(256, 1)
gemm_bf16(const __nv_bfloat16* __restrict__ A, int lda, long sA,
          const __nv_bfloat16* __restrict__ B, int ldb, long sB,
          void* __restrict__ Cv, int ldc, long sC,
          int Kdim,
          const float* __restrict__ R, int ldr) {
    const int mb = blockIdx.y, nb = blockIdx.x;
    if (CSKIP && 2 * nb > mb) return;   // fully-masked upper-triangular score block

    A += (long)blockIdx.z * sA;
    B += (long)blockIdx.z * sB;

    const int kend = CKLIM ? min(Kdim, (mb + 1) * BM) : Kdim;
    const int nK = kend >> 5;   // BK = 32; >= 4 for all our shapes

    extern __shared__ __align__(16) __nv_bfloat16 sm[];
    // stage st: A at st*STAGE_ELEMS (layout [128][40]),
    //           B at st*STAGE_ELEMS + ASTRIDE
    //           (BKMAJ ? [256 n][40 k] : [32 k][264 n])
    const uint32_t smBase = (uint32_t)__cvta_generic_to_shared(sm);

    const int tid = threadIdx.x;
    const int warp = tid >> 5, lane = tid & 31;
    const int gid = lane >> 2, tig = lane & 3;
    const int wm = (warp & 1) * 64, wn = (warp >> 1) * 64;
    const int bm0 = mb * BM, bn0 = nb * BN;

    float c[4][8][4];
#pragma unroll
    for (int i = 0; i < 4; i++)
#pragma unroll
        for (int j = 0; j < 8; j++)
#pragma unroll
            for (int k = 0; k < 4; k++) c[i][j][k] = 0.f;

    // ldmatrix per-lane coordinates
    const int arow = (lane & 7) + ((lane >> 3) & 1) * 8;
    const int acol = ((lane >> 4) & 1) * 8;
    const int ln8 = lane & 7, sel = lane >> 3;
    // BKMAJ=true  (x4 non-trans): rows are n, 16B along k
    const int bt_row = ((sel >> 1) & 1) * 8 + ln8;   // n offset within 16-tile
    const int bt_col = (sel & 1) * 8;                // k-half
    // BKMAJ=false (x4 trans): rows are k, cols are n
    const int bf_row = (sel & 1) * 8 + ln8;          // k offset within 16
    const int bf_col = ((sel >> 1) & 1) * 8;         // n offset within 16-tile

    auto fillA = [&](int st, int k0) {
        const uint32_t base = smBase + st * STAGE_ELEMS * 2;
#pragma unroll
        for (int p = 0; p < 2; p++) {
            int fid = tid + p * 256;
            int r = fid >> 2, kq = fid & 3;
            cpa16(base + (r * 40 + kq * 8) * 2,
                  A + (size_t)(bm0 + r) * lda + k0 + kq * 8);
        }
    };
    auto fillB = [&](int st, int k0) {
        const uint32_t base = smBase + (st * STAGE_ELEMS + ASTRIDE) * 2;
#pragma unroll
        for (int p = 0; p < 4; p++) {
            int fid = tid + p * 256;
            if (BKMAJ) {
                int r = fid >> 2, kq = fid & 3;
                cpa16(base + (r * 40 + kq * 8) * 2,
                      B + (size_t)(bn0 + r) * ldb + k0 + kq * 8);
            } else {
                int kr = fid >> 5, nq = fid & 31;
                cpa16(base + (kr * 264 + nq * 8) * 2,
                      B + (size_t)(k0 + kr) * ldb + bn0 + nq * 8);
            }
        }
    };

    // prologue: fill stages 0..3
#pragma unroll
    for (int st = 0; st < STAGES - 1; st++) {
        if (st < nK) { fillA(st, st * BK); fillB(st, st * BK); }
        cpa_commit();
    }

    int buf = 0, fb = STAGES - 1;
    for (int kt = 0; kt < nK; kt++) {
        cpa_wait<STAGES - 2>();
        __syncthreads();

        const uint32_t aS = smBase + buf * STAGE_ELEMS * 2;
        const uint32_t bS = aS + ASTRIDE * 2;

#pragma unroll
        for (int kc = 0; kc < 2; kc++) {
            const int kk = kc * 16;
            uint32_t af[4][4], bfr[4][4];
#pragma unroll
            for (int mf = 0; mf < 4; mf++) {
                uint32_t a = aS + ((wm + mf * 16 + arow) * 40 + acol + kk) * 2;
                asm volatile("ldmatrix.sync.aligned.m8n8.x4.shared.b16 {%0,%1,%2,%3},[%4];"
                    : "=r"(af[mf][0]), "=r"(af[mf][1]), "=r"(af[mf][2]), "=r"(af[mf][3])
                    : "r"(a));
            }
#pragma unroll
            for (int nfp = 0; nfp < 4; nfp++) {
                if (BKMAJ) {
                    uint32_t a = bS + ((wn + nfp * 16 + bt_row) * 40 + kk + bt_col) * 2;
                    asm volatile("ldmatrix.sync.aligned.m8n8.x4.shared.b16 {%0,%1,%2,%3},[%4];"
                        : "=r"(bfr[nfp][0]), "=r"(bfr[nfp][1]),
                          "=r"(bfr[nfp][2]), "=r"(bfr[nfp][3])
                        : "r"(a));
                } else {
                    uint32_t a = bS + ((kk + bf_row) * 264 + wn + nfp * 16 + bf_col) * 2;
                    asm volatile("ldmatrix.sync.aligned.m8n8.x4.trans.shared.b16 {%0,%1,%2,%3},[%4];"
                        : "=r"(bfr[nfp][0]), "=r"(bfr[nfp][1]),
                          "=r"(bfr[nfp][2]), "=r"(bfr[nfp][3])
                        : "r"(a));
                }
            }
#pragma unroll
            for (int mf = 0; mf < 4; mf++)
#pragma unroll
                for (int nf = 0; nf < 8; nf++) {
                    asm volatile(
                        "mma.sync.aligned.m16n8k16.row.col.f32.bf16.bf16.f32 "
                        "{%0,%1,%2,%3},{%4,%5,%6,%7},{%8,%9},{%0,%1,%2,%3};"
                        : "+f"(c[mf][nf][0]), "+f"(c[mf][nf][1]),
                          "+f"(c[mf][nf][2]), "+f"(c[mf][nf][3])
                        : "r"(af[mf][0]), "r"(af[mf][1]), "r"(af[mf][2]), "r"(af[mf][3]),
                          "r"(bfr[nf >> 1][(nf & 1) * 2]), "r"(bfr[nf >> 1][(nf & 1) * 2 + 1]));
                }
        }

        // fill stage kt+4 (buffer last computed at iter kt-1; safe after top sync)
        const int kf = kt + STAGES - 1;
        if (kf < nK) { fillA(fb, kf * BK); fillB(fb, kf * BK); }
        cpa_commit();
        buf = (buf + 1 == STAGES) ? 0 : buf + 1;
        fb  = (fb  + 1 == STAGES) ? 0 : fb  + 1;
    }

    // epilogue
    if (EPI == 2) {
        __nv_bfloat16* C = (__nv_bfloat16*)Cv + (long)blockIdx.z * sC;
#pragma unroll
        for (int mf = 0; mf < 4; mf++) {
            const int r0 = bm0 + wm + mf * 16 + gid;
#pragma unroll
            for (int nf = 0; nf < 8; nf++) {
                const int cc = bn0 + wn + nf * 8 + tig * 2;
                __nv_bfloat162 v0 = __float22bfloat162_rn(make_float2(c[mf][nf][0], c[mf][nf][1]));
                __nv_bfloat162 v1 = __float22bfloat162_rn(make_float2(c[mf][nf][2], c[mf][nf][3]));
                *reinterpret_cast<__nv_bfloat162*>(C + (size_t)r0 * ldc + cc) = v0;
                *reinterpret_cast<__nv_bfloat162*>(C + (size_t)(r0 + 8) * ldc + cc) = v1;
            }
        }
    } else {
        float* C = (float*)Cv + (long)blockIdx.z * sC;
#pragma unroll
        for (int mf = 0; mf < 4; mf++) {
            const int r0 = bm0 + wm + mf * 16 + gid;
#pragma unroll
            for (int nf = 0; nf < 8; nf++) {
                const int cc = bn0 + wn + nf * 8 + tig * 2;
                float2 v0 = make_float2(c[mf][nf][0], c[mf][nf][1]);
                float2 v1 = make_float2(c[mf][nf][2], c[mf][nf][3]);
                if (EPI == 1) {
                    const float2 q0 = *reinterpret_cast<const float2*>(R + (size_t)r0 * ldr + cc);
                    const float2 q1 = *reinterpret_cast<const float2*>(R + (size_t)(r0 + 8) * ldr + cc);
                    v0.x += q0.x; v0.y += q0.y;
                    v1.x += q1.x; v1.y += q1.y;
                }
                *reinterpret_cast<float2*>(C + (size_t)r0 * ldc + cc) = v0;
                *reinterpret_cast<float2*>(C + (size_t)(r0 + 8) * ldc + cc) = v1;
            }
        }
    }
}

// ---------------- launch ------------------------------------------------------
extern "C" void kernel_launch(void* const* d_in, const int* in_sizes, int n_in,
                              void* d_out, int out_size) {
    const float* x     = (const float*)d_in[0];
    const float* qkvw  = (const float*)d_in[1];
    const float* ow    = (const float*)d_in[2];
    const float* gamma = (const float*)d_in[3];
    const float* beta  = (const float*)d_in[4];
    float* out = (float*)d_out;

    __nv_bfloat16 *xn, *wqkv, *wo, *qkv, *pr, *av;
    float *sc;
    cudaGetSymbolAddress((void**)&xn,   g_xn);
    cudaGetSymbolAddress((void**)&wqkv, g_wqkv);
    cudaGetSymbolAddress((void**)&wo,   g_wo);
    cudaGetSymbolAddress((void**)&qkv,  g_qkv);
    cudaGetSymbolAddress((void**)&sc,   g_sc);
    cudaGetSymbolAddress((void**)&pr,   g_pr);
    cudaGetSymbolAddress((void**)&av,   g_av);

    cudaFuncSetAttribute(gemm_bf16<false, 2, false, false>,
                         cudaFuncAttributeMaxDynamicSharedMemorySize, SMEM_BYTES);
    cudaFuncSetAttribute(gemm_bf16<true,  0, true,  false>,
                         cudaFuncAttributeMaxDynamicSharedMemorySize, SMEM_BYTES);
    cudaFuncSetAttribute(gemm_bf16<false, 2, false, true>,
                         cudaFuncAttributeMaxDynamicSharedMemorySize, SMEM_BYTES);
    cudaFuncSetAttribute(gemm_bf16<false, 1, false, false>,
                         cudaFuncAttributeMaxDynamicSharedMemorySize, SMEM_BYTES);

    const int ROWS = BATCH * SEQ;  // 8192
    const long sQKV = (long)SEQ * NQKV;
    const long sSS  = (long)SEQ * SEQ;
    const long sSH  = (long)SEQ * HID;

    // 1) convert weights to bf16
    cvt_kernel<<<(HID * NQKV / 4 + 255) / 256, 256>>>(
        (const float4*)qkvw, (uint32_t*)wqkv, HID * NQKV / 4);
    cvt_kernel<<<(HID * HID / 4 + 255) / 256, 256>>>(
        (const float4*)ow, (uint32_t*)wo, HID * HID / 4);

    // 2) LayerNorm -> bf16
    ln_kernel<<<ROWS, 256>>>(x, gamma, beta, xn);

    // 3) QKV projection: [8192,2048] @ [2048,6144] -> bf16
    gemm_bf16<false, 2, false, false><<<dim3(NQKV / BN, ROWS / BM, 1), 256, SMEM_BYTES>>>(
        xn, HID, 0, wqkv, NQKV, 0, qkv, NQKV, 0, HID, nullptr, 0);

    // 4) scores = Q @ K^T per batch (skip fully-masked blocks) -> fp32
    gemm_bf16<true, 0, true, false><<<dim3(SEQ / BN, SEQ / BM, BATCH), 256, SMEM_BYTES>>>(
        qkv, NQKV, sQKV, qkv + HID, NQKV, sQKV, sc, SEQ, sSS, HID, nullptr, 0);

    // 5) causal softmax (scale fused) -> bf16 probs, zeroed tail
    softmax_kernel<<<ROWS, 256>>>(sc, pr, 1.0f / sqrtf((float)HID));

    // 6) attn @ V per batch (K-loop clipped at diagonal) -> bf16
    gemm_bf16<false, 2, false, true><<<dim3(HID / BN, SEQ / BM, BATCH), 256, SMEM_BYTES>>>(
        pr, SEQ, sSS, qkv + 2 * HID, NQKV, sQKV, av, HID, sSH, SEQ, nullptr, 0);

    // 7) O projection + residual: [8192,2048] @ [2048,2048] + x -> fp32 out
    gemm_bf16<false, 1, false, false><<<dim3(HID / BN, ROWS / BM, 1), 256, SMEM_BYTES>>>(
        av, HID, 0, wo, HID, 0, out, HID, 0, HID, x, HID);
}

// round 6
// speedup vs baseline: 1.0266x; 1.0266x over previous
#include <cuda_runtime.h>
#include <cuda_bf16.h>
#include <cstdint>
#include <math.h>

#define HID  2048
#define SEQ  2048
#define BATCH 4
#define NQKV 6144   // 3*HID

#define STAGES 5
#define SSTRIDE 5120          // bf16 elems per operand per stage
#define SMEM_BYTES (2 * STAGES * SSTRIDE * 2)   // 102400

// ---------------- scratch (device globals; no allocations allowed) ----------
__device__ __align__(16) __nv_bfloat16 g_xn  [BATCH * SEQ * HID];    // 32 MB
__device__ __align__(16) __nv_bfloat16 g_wqkv[HID * NQKV];           // 24 MB
__device__ __align__(16) __nv_bfloat16 g_wo  [HID * HID];            //  8 MB
__device__ __align__(16) __nv_bfloat16 g_qkv [BATCH * SEQ * NQKV];   // 96 MB
__device__ __align__(16) float         g_sc  [BATCH * SEQ * SEQ];    // 64 MB
__device__ __align__(16) __nv_bfloat16 g_pr  [BATCH * SEQ * SEQ];    // 32 MB
__device__ __align__(16) __nv_bfloat16 g_av  [BATCH * SEQ * HID];    // 32 MB

// ---------------- helpers ----------------------------------------------------
__device__ __forceinline__ void cpa16(uint32_t dst, const void* src) {
    asm volatile("cp.async.cg.shared.global [%0], [%1], 16;" :: "r"(dst), "l"(src));
}
__device__ __forceinline__ void cpa_commit() {
    asm volatile("cp.async.commit_group;");
}
template <int N>
__device__ __forceinline__ void cpa_wait() {
    asm volatile("cp.async.wait_group %0;" :: "n"(N));
}

// ---------------- fp32 -> bf16 convert ---------------------------------------
__global__ void cvt_kernel(const float4* __restrict__ in, uint32_t* __restrict__ out, int n4) {
    int i = blockIdx.x * blockDim.x + threadIdx.x;
    if (i < n4) {
        float4 v = in[i];
        __nv_bfloat162 a = __float22bfloat162_rn(make_float2(v.x, v.y));
        __nv_bfloat162 b = __float22bfloat162_rn(make_float2(v.z, v.w));
        out[i * 2 + 0] = *reinterpret_cast<uint32_t*>(&a);
        out[i * 2 + 1] = *reinterpret_cast<uint32_t*>(&b);
    }
}

// ---------------- LayerNorm: one block per row, bf16 out ---------------------
__global__ void ln_kernel(const float* __restrict__ x,
                          const float* __restrict__ gamma,
                          const float* __restrict__ beta,
                          __nv_bfloat16* __restrict__ out) {
    const int row = blockIdx.x;
    const float* xr = x + (size_t)row * HID;
    __nv_bfloat16* orow = out + (size_t)row * HID;
    const int tid = threadIdx.x;

    float v[8];
    float s = 0.f, s2 = 0.f;
#pragma unroll
    for (int i = 0; i < 8; i++) {
        float val = xr[tid + i * 256];
        v[i] = val; s += val; s2 += val * val;
    }
    __shared__ float red[2][8];
#pragma unroll
    for (int o = 16; o > 0; o >>= 1) {
        s  += __shfl_down_sync(0xffffffffu, s,  o);
        s2 += __shfl_down_sync(0xffffffffu, s2, o);
    }
    const int w = tid >> 5, l = tid & 31;
    if (l == 0) { red[0][w] = s; red[1][w] = s2; }
    __syncthreads();
    if (w == 0) {
        float a  = red[0][l & 7];
        float b2 = red[1][l & 7];
#pragma unroll
        for (int o = 4; o > 0; o >>= 1) {
            a  += __shfl_down_sync(0xffffffffu, a,  o);
            b2 += __shfl_down_sync(0xffffffffu, b2, o);
        }
        if (l == 0) { red[0][0] = a; red[1][0] = b2; }
    }
    __syncthreads();
    const float mean = red[0][0] * (1.f / HID);
    const float var  = red[1][0] * (1.f / HID) - mean * mean;
    const float rstd = rsqrtf(var + 1e-5f);
#pragma unroll
    for (int i = 0; i < 8; i++) {
        int h = tid + i * 256;
        orow[h] = __float2bfloat16((v[i] - mean) * rstd * gamma[h] + beta[h]);
    }
}

// ---------------- causal softmax: fp32 scores in, bf16 probs out -------------
// Zeroes only up to the 128-aligned end of the diagonal block (PV clips there).
__global__ void softmax_kernel(float* __restrict__ sc,
                               __nv_bfloat16* __restrict__ pr, float scale) {
    const int row = blockIdx.x;            // b*SEQ + q
    const int q = row & (SEQ - 1);
    float* p = sc + (size_t)row * SEQ;
    __nv_bfloat16* po = pr + (size_t)row * SEQ;
    const int n = q + 1;
    const int nend = ((q >> 7) + 1) << 7;  // PV reads only [0, nend)
    const int tid = threadIdx.x;
    __shared__ float red[8];

    float mx = -1e30f;
    for (int t = tid; t < n; t += 256) mx = fmaxf(mx, p[t] * scale);
#pragma unroll
    for (int o = 16; o > 0; o >>= 1) mx = fmaxf(mx, __shfl_down_sync(0xffffffffu, mx, o));
    if ((tid & 31) == 0) red[tid >> 5] = mx;
    __syncthreads();
    if (tid < 32) {
        float a = red[tid & 7];
#pragma unroll
        for (int o = 4; o > 0; o >>= 1) a = fmaxf(a, __shfl_down_sync(0xffffffffu, a, o));
        if (tid == 0) red[0] = a;
    }
    __syncthreads();
    mx = red[0];
    __syncthreads();

    float sum = 0.f;
    for (int t = tid; t < n; t += 256) {
        float e = __expf(p[t] * scale - mx);
        p[t] = e;
        sum += e;
    }
#pragma unroll
    for (int o = 16; o > 0; o >>= 1) sum += __shfl_down_sync(0xffffffffu, sum, o);
    if ((tid & 31) == 0) red[tid >> 5] = sum;
    __syncthreads();
    if (tid < 32) {
        float a = red[tid & 7];
#pragma unroll
        for (int o = 4; o > 0; o >>= 1) a += __shfl_down_sync(0xffffffffu, a, o);
        if (tid == 0) red[0] = a;
    }
    __syncthreads();
    const float inv = 1.f / red[0];
    for (int t = tid; t < n; t += 256) po[t] = __float2bfloat16(p[t] * inv);
    for (int t = n + tid; t < nend; t += 256) po[t] = __float2bfloat16(0.f);
}

// ---------------- bf16 tensor-core GEMM (5-stage cp.async pipeline) ----------
// C[M,N] = A[M,K] @ B. A row-major bf16 (lda).
// BKMAJ=true:  B stored [N,K] k-contig (ldb) -> A @ B^T.
// BKMAJ=false: B stored [K,N] n-contig (ldb).
// EPI: 0 = fp32 out, 1 = fp32 out + residual R, 2 = bf16 out.
// Block 128x128x32, 8 warps of 64x32, m16n8k16 bf16 mma, 2 CTAs/SM.
template <bool BKMAJ, int EPI, bool CSKIP, bool CKLIM>
__global__ void __launch_bounds__(256, 2)
gemm_bf16(const __nv_bfloat16* __restrict__ A, int lda, long sA,
          const __nv_bfloat16* __restrict__ B, int ldb, long sB,
          void* __restrict__ Cv, int ldc, long sC,
          int Kdim,
          const float* __restrict__ R, int ldr) {
    const int mb = blockIdx.y, nb = blockIdx.x;
    if (CSKIP && nb > mb) return;   // fully-masked upper-triangular score block

    A += (long)blockIdx.z * sA;
    B += (long)blockIdx.z * sB;

    const int kend = CKLIM ? min(Kdim, (mb + 1) * 128) : Kdim;
    const int nK = kend >> 5;   // BK = 32; >= 4 for all our shapes

    extern __shared__ __align__(16) __nv_bfloat16 sm[];
    // A stages: sm[st*SSTRIDE], layout [128 rows][40]
    // B stages: sm[STAGES*SSTRIDE + st*SSTRIDE],
    //           BKMAJ ? [128 n][40 k] : [32 k][136 n]
    const uint32_t smBase = (uint32_t)__cvta_generic_to_shared(sm);
    const uint32_t aBase = smBase;
    const uint32_t bBase = smBase + STAGES * SSTRIDE * 2;

    const int tid = threadIdx.x;
    const int warp = tid >> 5, lane = tid & 31;
    const int gid = lane >> 2, tig = lane & 3;
    const int wm = (warp & 1) * 64, wn = (warp >> 1) * 32;
    const int bm0 = mb * 128, bn0 = nb * 128;

    float c[4][4][4];
#pragma unroll
    for (int i = 0; i < 4; i++)
#pragma unroll
        for (int j = 0; j < 4; j++)
#pragma unroll
            for (int k = 0; k < 4; k++) c[i][j][k] = 0.f;

    // ldmatrix per-lane coordinates
    const int arow = (lane & 7) + ((lane >> 3) & 1) * 8;
    const int acol = ((lane >> 4) & 1) * 8;
    const int ln8 = lane & 7, sel = lane >> 3;
    // BKMAJ=true  (x4 non-trans): rows are n, 16B along k
    const int bt_row = ((sel >> 1) & 1) * 8 + ln8;   // n offset within 16-tile
    const int bt_col = (sel & 1) * 8;                // k-half
    // BKMAJ=false (x4 trans): rows are k, cols are n
    const int bf_row = (sel & 1) * 8 + ln8;          // k offset within 16
    const int bf_col = ((sel >> 1) & 1) * 8;         // n offset within 16-tile

    auto fillA = [&](int st, int k0) {
#pragma unroll
        for (int p = 0; p < 2; p++) {
            int fid = tid + p * 256;
            int r = fid >> 2, kq = fid & 3;
            cpa16(aBase + (st * SSTRIDE + r * 40 + kq * 8) * 2,
                  A + (size_t)(bm0 + r) * lda + k0 + kq * 8);
        }
    };
    auto fillB = [&](int st, int k0) {
#pragma unroll
        for (int p = 0; p < 2; p++) {
            int fid = tid + p * 256;
            if (BKMAJ) {
                int r = fid >> 2, kq = fid & 3;
                cpa16(bBase + (st * SSTRIDE + r * 40 + kq * 8) * 2,
                      B + (size_t)(bn0 + r) * ldb + k0 + kq * 8);
            } else {
                int kr = fid >> 4, nq = fid & 15;
                cpa16(bBase + (st * SSTRIDE + kr * 136 + nq * 8) * 2,
                      B + (size_t)(k0 + kr) * ldb + bn0 + nq * 8);
            }
        }
    };

    // prologue: fill stages 0..3
#pragma unroll
    for (int st = 0; st < STAGES - 1; st++) {
        fillA(st, st * 32); fillB(st, st * 32);
        cpa_commit();
    }

    int buf = 0, fb = STAGES - 1;
    for (int kt = 0; kt < nK; kt++) {
        cpa_wait<STAGES - 2>();
        __syncthreads();

        // EARLY fill: start stage kt+4's copies before this iter's MMA work.
        // Buffer fb was consumed at iter kt-1; the sync above makes reuse safe.
        const int kf = kt + STAGES - 1;
        if (kf < nK) { fillA(fb, kf * 32); fillB(fb, kf * 32); }
        cpa_commit();

        const uint32_t aS = aBase + buf * SSTRIDE * 2;
        const uint32_t bS = bBase + buf * SSTRIDE * 2;

#pragma unroll
        for (int kc = 0; kc < 2; kc++) {
            const int kk = kc * 16;
            uint32_t af[4][4], bfr[2][4];
#pragma unroll
            for (int mf = 0; mf < 4; mf++) {
                uint32_t a = aS + ((wm + mf * 16 + arow) * 40 + acol + kk) * 2;
                asm volatile("ldmatrix.sync.aligned.m8n8.x4.shared.b16 {%0,%1,%2,%3},[%4];"
                    : "=r"(af[mf][0]), "=r"(af[mf][1]), "=r"(af[mf][2]), "=r"(af[mf][3])
                    : "r"(a));
            }
#pragma unroll
            for (int nfp = 0; nfp < 2; nfp++) {
                if (BKMAJ) {
                    uint32_t a = bS + ((wn + nfp * 16 + bt_row) * 40 + kk + bt_col) * 2;
                    asm volatile("ldmatrix.sync.aligned.m8n8.x4.shared.b16 {%0,%1,%2,%3},[%4];"
                        : "=r"(bfr[nfp][0]), "=r"(bfr[nfp][1]),
                          "=r"(bfr[nfp][2]), "=r"(bfr[nfp][3])
                        : "r"(a));
                } else {
                    uint32_t a = bS + ((kk + bf_row) * 136 + wn + nfp * 16 + bf_col) * 2;
                    asm volatile("ldmatrix.sync.aligned.m8n8.x4.trans.shared.b16 {%0,%1,%2,%3},[%4];"
                        : "=r"(bfr[nfp][0]), "=r"(bfr[nfp][1]),
                          "=r"(bfr[nfp][2]), "=r"(bfr[nfp][3])
                        : "r"(a));
                }
            }
#pragma unroll
            for (int mf = 0; mf < 4; mf++)
#pragma unroll
                for (int nf = 0; nf < 4; nf++) {
                    asm volatile(
                        "mma.sync.aligned.m16n8k16.row.col.f32.bf16.bf16.f32 "
                        "{%0,%1,%2,%3},{%4,%5,%6,%7},{%8,%9},{%0,%1,%2,%3};"
                        : "+f"(c[mf][nf][0]), "+f"(c[mf][nf][1]),
                          "+f"(c[mf][nf][2]), "+f"(c[mf][nf][3])
                        : "r"(af[mf][0]), "r"(af[mf][1]), "r"(af[mf][2]), "r"(af[mf][3]),
                          "r"(bfr[nf >> 1][(nf & 1) * 2]), "r"(bfr[nf >> 1][(nf & 1) * 2 + 1]));
                }
        }

        buf = (buf + 1 == STAGES) ? 0 : buf + 1;
        fb  = (fb  + 1 == STAGES) ? 0 : fb  + 1;
    }

    // epilogue
    if (EPI == 2) {
        __nv_bfloat16* C = (__nv_bfloat16*)Cv + (long)blockIdx.z * sC;
#pragma unroll
        for (int mf = 0; mf < 4; mf++) {
            const int r0 = bm0 + wm + mf * 16 + gid;
#pragma unroll
            for (int nf = 0; nf < 4; nf++) {
                const int cc = bn0 + wn + nf * 8 + tig * 2;
                __nv_bfloat162 v0 = __float22bfloat162_rn(make_float2(c[mf][nf][0], c[mf][nf][1]));
                __nv_bfloat162 v1 = __float22bfloat162_rn(make_float2(c[mf][nf][2], c[mf][nf][3]));
                *reinterpret_cast<__nv_bfloat162*>(C + (size_t)r0 * ldc + cc) = v0;
                *reinterpret_cast<__nv_bfloat162*>(C + (size_t)(r0 + 8) * ldc + cc) = v1;
            }
        }
    } else {
        float* C = (float*)Cv + (long)blockIdx.z * sC;
#pragma unroll
        for (int mf = 0; mf < 4; mf++) {
            const int r0 = bm0 + wm + mf * 16 + gid;
#pragma unroll
            for (int nf = 0; nf < 4; nf++) {
                const int cc = bn0 + wn + nf * 8 + tig * 2;
                float2 v0 = make_float2(c[mf][nf][0], c[mf][nf][1]);
                float2 v1 = make_float2(c[mf][nf][2], c[mf][nf][3]);
                if (EPI == 1) {
                    const float2 q0 = *reinterpret_cast<const float2*>(R + (size_t)r0 * ldr + cc);
                    const float2 q1 = *reinterpret_cast<const float2*>(R + (size_t)(r0 + 8) * ldr + cc);
                    v0.x += q0.x; v0.y += q0.y;
                    v1.x += q1.x; v1.y += q1.y;
                }
                *reinterpret_cast<float2*>(C + (size_t)r0 * ldc + cc) = v0;
                *reinterpret_cast<float2*>(C + (size_t)(r0 + 8) * ldc + cc) = v1;
            }
        }
    }
}

// ---------------- launch ------------------------------------------------------
extern "C" void kernel_launch(void* const* d_in, const int* in_sizes, int n_in,
                              void* d_out, int out_size) {
    const float* x     = (const float*)d_in[0];
    const float* qkvw  = (const float*)d_in[1];
    const float* ow    = (const float*)d_in[2];
    const float* gamma = (const float*)d_in[3];
    const float* beta  = (const float*)d_in[4];
    float* out = (float*)d_out;

    __nv_bfloat16 *xn, *wqkv, *wo, *qkv, *pr, *av;
    float *sc;
    cudaGetSymbolAddress((void**)&xn,   g_xn);
    cudaGetSymbolAddress((void**)&wqkv, g_wqkv);
    cudaGetSymbolAddress((void**)&wo,   g_wo);
    cudaGetSymbolAddress((void**)&qkv,  g_qkv);
    cudaGetSymbolAddress((void**)&sc,   g_sc);
    cudaGetSymbolAddress((void**)&pr,   g_pr);
    cudaGetSymbolAddress((void**)&av,   g_av);

    cudaFuncSetAttribute(gemm_bf16<false, 2, false, false>,
                         cudaFuncAttributeMaxDynamicSharedMemorySize, SMEM_BYTES);
    cudaFuncSetAttribute(gemm_bf16<true,  0, true,  false>,
                         cudaFuncAttributeMaxDynamicSharedMemorySize, SMEM_BYTES);
    cudaFuncSetAttribute(gemm_bf16<false, 2, false, true>,
                         cudaFuncAttributeMaxDynamicSharedMemorySize, SMEM_BYTES);
    cudaFuncSetAttribute(gemm_bf16<false, 1, false, false>,
                         cudaFuncAttributeMaxDynamicSharedMemorySize, SMEM_BYTES);

    const int ROWS = BATCH * SEQ;  // 8192
    const long sQKV = (long)SEQ * NQKV;
    const long sSS  = (long)SEQ * SEQ;
    const long sSH  = (long)SEQ * HID;

    // 1) convert weights to bf16
    cvt_kernel<<<(HID * NQKV / 4 + 255) / 256, 256>>>(
        (const float4*)qkvw, (uint32_t*)wqkv, HID * NQKV / 4);
    cvt_kernel<<<(HID * HID / 4 + 255) / 256, 256>>>(
        (const float4*)ow, (uint32_t*)wo, HID * HID / 4);

    // 2) LayerNorm -> bf16
    ln_kernel<<<ROWS, 256>>>(x, gamma, beta, xn);

    // 3) QKV projection: [8192,2048] @ [2048,6144] -> bf16
    gemm_bf16<false, 2, false, false><<<dim3(NQKV / 128, ROWS / 128, 1), 256, SMEM_BYTES>>>(
        xn, HID, 0, wqkv, NQKV, 0, qkv, NQKV, 0, HID, nullptr, 0);

    // 4) scores = Q @ K^T per batch (skip fully-masked blocks) -> fp32
    gemm_bf16<true, 0, true, false><<<dim3(SEQ / 128, SEQ / 128, BATCH), 256, SMEM_BYTES>>>(
        qkv, NQKV, sQKV, qkv + HID, NQKV, sQKV, sc, SEQ, sSS, HID, nullptr, 0);

    // 5) causal softmax (scale fused) -> bf16 probs, zeroed to diag block edge
    softmax_kernel<<<ROWS, 256>>>(sc, pr, 1.0f / sqrtf((float)HID));

    // 6) attn @ V per batch (K-loop clipped at diagonal) -> bf16
    gemm_bf16<false, 2, false, true><<<dim3(HID / 128, SEQ / 128, BATCH), 256, SMEM_BYTES>>>(
        pr, SEQ, sSS, qkv + 2 * HID, NQKV, sQKV, av, HID, sSH, SEQ, nullptr, 0);

    // 7) O projection + residual: [8192,2048] @ [2048,2048] + x -> fp32 out
    gemm_bf16<false, 1, false, false><<<dim3(HID / 128, ROWS / 128, 1), 256, SMEM_BYTES>>>(
        av, HID, 0, wo, HID, 0, out, HID, 0, HID, x, HID);
}

// round 7
// speedup vs baseline: 1.0625x; 1.0350x over previous
#include <cuda_runtime.h>
#include <cuda_bf16.h>
#include <cstdint>
#include <math.h>

#define HID  2048
#define SEQ  2048
#define BATCH 4
#define NQKV 6144   // 3*HID

#define STAGES 3
#define BK 64
#define SSTRIDE 9216          // bf16 elems per operand per stage (128*72)
#define SMEM_BYTES (2 * STAGES * SSTRIDE * 2)   // 110592

// ---------------- scratch (device globals; no allocations allowed) ----------
__device__ __align__(16) __nv_bfloat16 g_xn  [BATCH * SEQ * HID];    // 32 MB
__device__ __align__(16) __nv_bfloat16 g_wqkv[HID * NQKV];           // 24 MB
__device__ __align__(16) __nv_bfloat16 g_wo  [HID * HID];            //  8 MB
__device__ __align__(16) __nv_bfloat16 g_qkv [BATCH * SEQ * NQKV];   // 96 MB
__device__ __align__(16) float         g_sc  [BATCH * SEQ * SEQ];    // 64 MB
__device__ __align__(16) __nv_bfloat16 g_pr  [BATCH * SEQ * SEQ];    // 32 MB
__device__ __align__(16) __nv_bfloat16 g_av  [BATCH * SEQ * HID];    // 32 MB

// ---------------- helpers ----------------------------------------------------
__device__ __forceinline__ void cpa16(uint32_t dst, const void* src) {
    asm volatile("cp.async.cg.shared.global [%0], [%1], 16;" :: "r"(dst), "l"(src));
}
__device__ __forceinline__ void cpa_commit() {
    asm volatile("cp.async.commit_group;");
}
template <int N>
__device__ __forceinline__ void cpa_wait() {
    asm volatile("cp.async.wait_group %0;" :: "n"(N));
}

// ---------------- fp32 -> bf16 convert ---------------------------------------
__global__ void cvt_kernel(const float4* __restrict__ in, uint32_t* __restrict__ out, int n4) {
    int i = blockIdx.x * blockDim.x + threadIdx.x;
    if (i < n4) {
        float4 v = in[i];
        __nv_bfloat162 a = __float22bfloat162_rn(make_float2(v.x, v.y));
        __nv_bfloat162 b = __float22bfloat162_rn(make_float2(v.z, v.w));
        out[i * 2 + 0] = *reinterpret_cast<uint32_t*>(&a);
        out[i * 2 + 1] = *reinterpret_cast<uint32_t*>(&b);
    }
}

// ---------------- LayerNorm: one block per row, bf16 out ---------------------
__global__ void ln_kernel(const float* __restrict__ x,
                          const float* __restrict__ gamma,
                          const float* __restrict__ beta,
                          __nv_bfloat16* __restrict__ out) {
    const int row = blockIdx.x;
    const float* xr = x + (size_t)row * HID;
    __nv_bfloat16* orow = out + (size_t)row * HID;
    const int tid = threadIdx.x;

    float v[8];
    float s = 0.f, s2 = 0.f;
#pragma unroll
    for (int i = 0; i < 8; i++) {
        float val = xr[tid + i * 256];
        v[i] = val; s += val; s2 += val * val;
    }
    __shared__ float red[2][8];
#pragma unroll
    for (int o = 16; o > 0; o >>= 1) {
        s  += __shfl_down_sync(0xffffffffu, s,  o);
        s2 += __shfl_down_sync(0xffffffffu, s2, o);
    }
    const int w = tid >> 5, l = tid & 31;
    if (l == 0) { red[0][w] = s; red[1][w] = s2; }
    __syncthreads();
    if (w == 0) {
        float a  = red[0][l & 7];
        float b2 = red[1][l & 7];
#pragma unroll
        for (int o = 4; o > 0; o >>= 1) {
            a  += __shfl_down_sync(0xffffffffu, a,  o);
            b2 += __shfl_down_sync(0xffffffffu, b2, o);
        }
        if (l == 0) { red[0][0] = a; red[1][0] = b2; }
    }
    __syncthreads();
    const float mean = red[0][0] * (1.f / HID);
    const float var  = red[1][0] * (1.f / HID) - mean * mean;
    const float rstd = rsqrtf(var + 1e-5f);
#pragma unroll
    for (int i = 0; i < 8; i++) {
        int h = tid + i * 256;
        orow[h] = __float2bfloat16((v[i] - mean) * rstd * gamma[h] + beta[h]);
    }
}

// ---------------- causal softmax: fp32 scores in, bf16 probs out -------------
// Zeroes only up to the 128-aligned end of the diagonal block (PV clips there).
__global__ void softmax_kernel(float* __restrict__ sc,
                               __nv_bfloat16* __restrict__ pr, float scale) {
    const int row = blockIdx.x;            // b*SEQ + q
    const int q = row & (SEQ - 1);
    float* p = sc + (size_t)row * SEQ;
    __nv_bfloat16* po = pr + (size_t)row * SEQ;
    const int n = q + 1;
    const int nend = ((q >> 7) + 1) << 7;  // PV reads only [0, nend)
    const int tid = threadIdx.x;
    __shared__ float red[8];

    float mx = -1e30f;
    for (int t = tid; t < n; t += 256) mx = fmaxf(mx, p[t] * scale);
#pragma unroll
    for (int o = 16; o > 0; o >>= 1) mx = fmaxf(mx, __shfl_down_sync(0xffffffffu, mx, o));
    if ((tid & 31) == 0) red[tid >> 5] = mx;
    __syncthreads();
    if (tid < 32) {
        float a = red[tid & 7];
#pragma unroll
        for (int o = 4; o > 0; o >>= 1) a = fmaxf(a, __shfl_down_sync(0xffffffffu, a, o));
        if (tid == 0) red[0] = a;
    }
    __syncthreads();
    mx = red[0];
    __syncthreads();

    float sum = 0.f;
    for (int t = tid; t < n; t += 256) {
        float e = __expf(p[t] * scale - mx);
        p[t] = e;
        sum += e;
    }
#pragma unroll
    for (int o = 16; o > 0; o >>= 1) sum += __shfl_down_sync(0xffffffffu, sum, o);
    if ((tid & 31) == 0) red[tid >> 5] = sum;
    __syncthreads();
    if (tid < 32) {
        float a = red[tid & 7];
#pragma unroll
        for (int o = 4; o > 0; o >>= 1) a += __shfl_down_sync(0xffffffffu, a, o);
        if (tid == 0) red[0] = a;
    }
    __syncthreads();
    const float inv = 1.f / red[0];
    for (int t = tid; t < n; t += 256) po[t] = __float2bfloat16(p[t] * inv);
    for (int t = n + tid; t < nend; t += 256) po[t] = __float2bfloat16(0.f);
}

// ---------------- bf16 tensor-core GEMM (3-stage, BK=64) ---------------------
// C[M,N] = A[M,K] @ B. A row-major bf16 (lda).
// BKMAJ=true:  B stored [N,K] k-contig (ldb) -> A @ B^T.
// BKMAJ=false: B stored [K,N] n-contig (ldb).
// EPI: 0 = fp32 out, 1 = fp32 out + residual R, 2 = bf16 out.
// Block 128x128x64, 8 warps of 64x32, m16n8k16 bf16 mma, 2 CTAs/SM.
template <bool BKMAJ, int EPI, bool CSKIP, bool CKLIM>
__global__ void __launch_bounds__(256, 2)
gemm_bf16(const __nv_bfloat16* __restrict__ A, int lda, long sA,
          const __nv_bfloat16* __restrict__ B, int ldb, long sB,
          void* __restrict__ Cv, int ldc, long sC,
          int Kdim,
          const float* __restrict__ R, int ldr) {
    const int mb = blockIdx.y, nb = blockIdx.x;
    if (CSKIP && nb > mb) return;   // fully-masked upper-triangular score block

    A += (long)blockIdx.z * sA;
    B += (long)blockIdx.z * sB;

    const int kend = CKLIM ? min(Kdim, (mb + 1) * 128) : Kdim;
    const int nK = kend >> 6;   // BK = 64; >= 2 for all our shapes

    extern __shared__ __align__(16) __nv_bfloat16 sm[];
    // A stages: sm[st*SSTRIDE], layout [128 rows][72]   (64 k + pad 8)
    // B stages: sm[STAGES*SSTRIDE + st*SSTRIDE],
    //           BKMAJ ? [128 n][72 k] : [64 k][136 n]
    const uint32_t smBase = (uint32_t)__cvta_generic_to_shared(sm);
    const uint32_t aBase = smBase;
    const uint32_t bBase = smBase + STAGES * SSTRIDE * 2;

    const int tid = threadIdx.x;
    const int warp = tid >> 5, lane = tid & 31;
    const int gid = lane >> 2, tig = lane & 3;
    const int wm = (warp & 1) * 64, wn = (warp >> 1) * 32;
    const int bm0 = mb * 128, bn0 = nb * 128;

    float c[4][4][4];
#pragma unroll
    for (int i = 0; i < 4; i++)
#pragma unroll
        for (int j = 0; j < 4; j++)
#pragma unroll
            for (int k = 0; k < 4; k++) c[i][j][k] = 0.f;

    // ldmatrix per-lane coordinates
    const int arow = (lane & 7) + ((lane >> 3) & 1) * 8;
    const int acol = ((lane >> 4) & 1) * 8;
    const int ln8 = lane & 7, sel = lane >> 3;
    // BKMAJ=true  (x4 non-trans): rows are n, 16B along k
    const int bt_row = ((sel >> 1) & 1) * 8 + ln8;   // n offset within 16-tile
    const int bt_col = (sel & 1) * 8;                // k-half
    // BKMAJ=false (x4 trans): rows are k, cols are n
    const int bf_row = (sel & 1) * 8 + ln8;          // k offset within 16
    const int bf_col = ((sel >> 1) & 1) * 8;         // n offset within 16-tile

    auto fillA = [&](int st, int k0) {
        // 128 rows x 64 k = 1024 16B-chunks, 4 per thread
#pragma unroll
        for (int p = 0; p < 4; p++) {
            int fid = tid + p * 256;
            int r = fid >> 3, kq = fid & 7;
            cpa16(aBase + (st * SSTRIDE + r * 72 + kq * 8) * 2,
                  A + (size_t)(bm0 + r) * lda + k0 + kq * 8);
        }
    };
    auto fillB = [&](int st, int k0) {
#pragma unroll
        for (int p = 0; p < 4; p++) {
            int fid = tid + p * 256;
            if (BKMAJ) {
                int r = fid >> 3, kq = fid & 7;
                cpa16(bBase + (st * SSTRIDE + r * 72 + kq * 8) * 2,
                      B + (size_t)(bn0 + r) * ldb + k0 + kq * 8);
            } else {
                int kr = fid >> 4, nq = fid & 15;
                cpa16(bBase + (st * SSTRIDE + kr * 136 + nq * 8) * 2,
                      B + (size_t)(k0 + kr) * ldb + bn0 + nq * 8);
            }
        }
    };

    // prologue: fill stages 0..1
#pragma unroll
    for (int st = 0; st < STAGES - 1; st++) {
        fillA(st, st * BK); fillB(st, st * BK);
        cpa_commit();
    }

    int buf = 0, fb = STAGES - 1;
    for (int kt = 0; kt < nK; kt++) {
        cpa_wait<STAGES - 2>();
        __syncthreads();

        // EARLY fill: start stage kt+2's copies before this iter's MMA work.
        const int kf = kt + STAGES - 1;
        if (kf < nK) { fillA(fb, kf * BK); fillB(fb, kf * BK); }
        cpa_commit();

        const uint32_t aS = aBase + buf * SSTRIDE * 2;
        const uint32_t bS = bBase + buf * SSTRIDE * 2;

#pragma unroll
        for (int kc = 0; kc < 4; kc++) {
            const int kk = kc * 16;
            uint32_t af[4][4], bfr[2][4];
#pragma unroll
            for (int mf = 0; mf < 4; mf++) {
                uint32_t a = aS + ((wm + mf * 16 + arow) * 72 + acol + kk) * 2;
                asm volatile("ldmatrix.sync.aligned.m8n8.x4.shared.b16 {%0,%1,%2,%3},[%4];"
                    : "=r"(af[mf][0]), "=r"(af[mf][1]), "=r"(af[mf][2]), "=r"(af[mf][3])
                    : "r"(a));
            }
#pragma unroll
            for (int nfp = 0; nfp < 2; nfp++) {
                if (BKMAJ) {
                    uint32_t a = bS + ((wn + nfp * 16 + bt_row) * 72 + kk + bt_col) * 2;
                    asm volatile("ldmatrix.sync.aligned.m8n8.x4.shared.b16 {%0,%1,%2,%3},[%4];"
                        : "=r"(bfr[nfp][0]), "=r"(bfr[nfp][1]),
                          "=r"(bfr[nfp][2]), "=r"(bfr[nfp][3])
                        : "r"(a));
                } else {
                    uint32_t a = bS + ((kk + bf_row) * 136 + wn + nfp * 16 + bf_col) * 2;
                    asm volatile("ldmatrix.sync.aligned.m8n8.x4.trans.shared.b16 {%0,%1,%2,%3},[%4];"
                        : "=r"(bfr[nfp][0]), "=r"(bfr[nfp][1]),
                          "=r"(bfr[nfp][2]), "=r"(bfr[nfp][3])
                        : "r"(a));
                }
            }
#pragma unroll
            for (int mf = 0; mf < 4; mf++)
#pragma unroll
                for (int nf = 0; nf < 4; nf++) {
                    asm volatile(
                        "mma.sync.aligned.m16n8k16.row.col.f32.bf16.bf16.f32 "
                        "{%0,%1,%2,%3},{%4,%5,%6,%7},{%8,%9},{%0,%1,%2,%3};"
                        : "+f"(c[mf][nf][0]), "+f"(c[mf][nf][1]),
                          "+f"(c[mf][nf][2]), "+f"(c[mf][nf][3])
                        : "r"(af[mf][0]), "r"(af[mf][1]), "r"(af[mf][2]), "r"(af[mf][3]),
                          "r"(bfr[nf >> 1][(nf & 1) * 2]), "r"(bfr[nf >> 1][(nf & 1) * 2 + 1]));
                }
        }

        buf = (buf + 1 == STAGES) ? 0 : buf + 1;
        fb  = (fb  + 1 == STAGES) ? 0 : fb  + 1;
    }

    // epilogue
    if (EPI == 2) {
        __nv_bfloat16* C = (__nv_bfloat16*)Cv + (long)blockIdx.z * sC;
#pragma unroll
        for (int mf = 0; mf < 4; mf++) {
            const int r0 = bm0 + wm + mf * 16 + gid;
#pragma unroll
            for (int nf = 0; nf < 4; nf++) {
                const int cc = bn0 + wn + nf * 8 + tig * 2;
                __nv_bfloat162 v0 = __float22bfloat162_rn(make_float2(c[mf][nf][0], c[mf][nf][1]));
                __nv_bfloat162 v1 = __float22bfloat162_rn(make_float2(c[mf][nf][2], c[mf][nf][3]));
                *reinterpret_cast<__nv_bfloat162*>(C + (size_t)r0 * ldc + cc) = v0;
                *reinterpret_cast<__nv_bfloat162*>(C + (size_t)(r0 + 8) * ldc + cc) = v1;
            }
        }
    } else {
        float* C = (float*)Cv + (long)blockIdx.z * sC;
#pragma unroll
        for (int mf = 0; mf < 4; mf++) {
            const int r0 = bm0 + wm + mf * 16 + gid;
#pragma unroll
            for (int nf = 0; nf < 4; nf++) {
                const int cc = bn0 + wn + nf * 8 + tig * 2;
                float2 v0 = make_float2(c[mf][nf][0], c[mf][nf][1]);
                float2 v1 = make_float2(c[mf][nf][2], c[mf][nf][3]);
                if (EPI == 1) {
                    const float2 q0 = *reinterpret_cast<const float2*>(R + (size_t)r0 * ldr + cc);
                    const float2 q1 = *reinterpret_cast<const float2*>(R + (size_t)(r0 + 8) * ldr + cc);
                    v0.x += q0.x; v0.y += q0.y;
                    v1.x += q1.x; v1.y += q1.y;
                }
                *reinterpret_cast<float2*>(C + (size_t)r0 * ldc + cc) = v0;
                *reinterpret_cast<float2*>(C + (size_t)(r0 + 8) * ldc + cc) = v1;
            }
        }
    }
}

// ---------------- launch ------------------------------------------------------
extern "C" void kernel_launch(void* const* d_in, const int* in_sizes, int n_in,
                              void* d_out, int out_size) {
    const float* x     = (const float*)d_in[0];
    const float* qkvw  = (const float*)d_in[1];
    const float* ow    = (const float*)d_in[2];
    const float* gamma = (const float*)d_in[3];
    const float* beta  = (const float*)d_in[4];
    float* out = (float*)d_out;

    __nv_bfloat16 *xn, *wqkv, *wo, *qkv, *pr, *av;
    float *sc;
    cudaGetSymbolAddress((void**)&xn,   g_xn);
    cudaGetSymbolAddress((void**)&wqkv, g_wqkv);
    cudaGetSymbolAddress((void**)&wo,   g_wo);
    cudaGetSymbolAddress((void**)&qkv,  g_qkv);
    cudaGetSymbolAddress((void**)&sc,   g_sc);
    cudaGetSymbolAddress((void**)&pr,   g_pr);
    cudaGetSymbolAddress((void**)&av,   g_av);

    cudaFuncSetAttribute(gemm_bf16<false, 2, false, false>,
                         cudaFuncAttributeMaxDynamicSharedMemorySize, SMEM_BYTES);
    cudaFuncSetAttribute(gemm_bf16<true,  0, true,  false>,
                         cudaFuncAttributeMaxDynamicSharedMemorySize, SMEM_BYTES);
    cudaFuncSetAttribute(gemm_bf16<false, 2, false, true>,
                         cudaFuncAttributeMaxDynamicSharedMemorySize, SMEM_BYTES);
    cudaFuncSetAttribute(gemm_bf16<false, 1, false, false>,
                         cudaFuncAttributeMaxDynamicSharedMemorySize, SMEM_BYTES);

    const int ROWS = BATCH * SEQ;  // 8192
    const long sQKV = (long)SEQ * NQKV;
    const long sSS  = (long)SEQ * SEQ;
    const long sSH  = (long)SEQ * HID;

    // 1) convert weights to bf16
    cvt_kernel<<<(HID * NQKV / 4 + 255) / 256, 256>>>(
        (const float4*)qkvw, (uint32_t*)wqkv, HID * NQKV / 4);
    cvt_kernel<<<(HID * HID / 4 + 255) / 256, 256>>>(
        (const float4*)ow, (uint32_t*)wo, HID * HID / 4);

    // 2) LayerNorm -> bf16
    ln_kernel<<<ROWS, 256>>>(x, gamma, beta, xn);

    // 3) QKV projection: [8192,2048] @ [2048,6144] -> bf16
    gemm_bf16<false, 2, false, false><<<dim3(NQKV / 128, ROWS / 128, 1), 256, SMEM_BYTES>>>(
        xn, HID, 0, wqkv, NQKV, 0, qkv, NQKV, 0, HID, nullptr, 0);

    // 4) scores = Q @ K^T per batch (skip fully-masked blocks) -> fp32
    gemm_bf16<true, 0, true, false><<<dim3(SEQ / 128, SEQ / 128, BATCH), 256, SMEM_BYTES>>>(
        qkv, NQKV, sQKV, qkv + HID, NQKV, sQKV, sc, SEQ, sSS, HID, nullptr, 0);

    // 5) causal softmax (scale fused) -> bf16 probs, zeroed to diag block edge
    softmax_kernel<<<ROWS, 256>>>(sc, pr, 1.0f / sqrtf((float)HID));

    // 6) attn @ V per batch (K-loop clipped at diagonal) -> bf16
    gemm_bf16<false, 2, false, true><<<dim3(HID / 128, SEQ / 128, BATCH), 256, SMEM_BYTES>>>(
        pr, SEQ, sSS, qkv + 2 * HID, NQKV, sQKV, av, HID, sSH, SEQ, nullptr, 0);

    // 7) O projection + residual: [8192,2048] @ [2048,2048] + x -> fp32 out
    gemm_bf16<false, 1, false, false><<<dim3(HID / 128, ROWS / 128, 1), 256, SMEM_BYTES>>>(
        av, HID, 0, wo, HID, 0, out, HID, 0, HID, x, HID);
}